// round 8
// baseline (speedup 1.0000x reference)
#include <cuda_runtime.h>
#include <cstdint>

#define BB 512
#define TT 4096
#define SS 64
#define MM 125
#define CHUNK 512                 // time-steps per producer/consumer chunk
#define NCHUNK (TT / CHUNK)       // 8

// packed f32x2 FMA — only reachable via PTX (ptxas never auto-fuses)
__device__ __forceinline__ void ffma2(float2& d, float2 a, float2 b, float2 c) {
    asm("fma.rn.f32x2 %0, %1, %2, %3;"
        : "=l"(*(unsigned long long*)&d)
        : "l"(*(unsigned long long*)&a),
          "l"(*(unsigned long long*)&b),
          "l"(*(unsigned long long*)&c));
}

// pair rendezvous: scanner warp s and decoder warp s+2, named barrier s+1
__device__ __forceinline__ void pair_bar(int s) {
    asm volatile("bar.sync %0, 64;" :: "r"(s + 1) : "memory");
}

// ---------------------------------------------------------------------------
// Fused kernel, 128 threads/CTA:
//   warps 0,1 : scanner warps, 2 chains each (interleaved for ILP)
//   warps 2,3 : decoder warps, stream + argmax-decode the 2 partner chains
// ---------------------------------------------------------------------------
__global__ void __launch_bounds__(128) fused_hmm_kernel(
    const float* __restrict__ x,
    const float* __restrict__ Ivec,
    const float* __restrict__ A,
    const float* __restrict__ Bm,
    float* __restrict__ out)
{
    __shared__ float2 sB2[MM * 32];                         // 32000 B
    __shared__ float sAlpha[4][2][SS];                      //  2048 B  (per chain slot)
    __shared__ unsigned char sObs[4][2][CHUNK];             //  4096 B  (per chain slot)

    const int tid  = threadIdx.x;
    const int w    = tid >> 5;          // 0..3
    const int lane = tid & 31;
    const int s    = w & 1;             // pair id (scanner s <-> decoder s+2)
    const int slot0 = 2 * s;            // chain slots in CTA
    const int slot1 = 2 * s + 1;
    const int b0   = blockIdx.x * 4 + slot0;
    const int b1   = blockIdx.x * 4 + slot1;

    // stage Bm into shared as (Bm[m][l], Bm[m][l+32]) pairs
    for (int i = tid; i < MM * 32; i += 128) {
        int m = i >> 5, l = i & 31;
        sB2[i] = make_float2(Bm[m * SS + l], Bm[m * SS + 32 + l]);
    }
    __syncthreads();

    if (w >= 2) {
        // ------------- decoder warp: chains b0 and b1 -------------
        const float4* xc0 = (const float4*)(x + (size_t)b0 * TT * MM);
        const float4* xc1 = (const float4*)(x + (size_t)b1 * TT * MM);
        for (int c = 0; c < NCHUNK; c++) {
            const unsigned jbase = c * (CHUNK * MM);
            const unsigned rbase = c * CHUNK;
#pragma unroll
            for (int half = 0; half < 2; half++) {
                unsigned char* dst = sObs[slot0 + half][c & 1];
                const float4* base = (half ? xc1 : xc0) + c * (CHUNK * MM / 4);
                for (int i = lane; i < CHUNK * MM / 4; i += 32) {
                    float4 v = __ldcs(base + i);
                    unsigned j = jbase + 4u * i;
                    if (v.x > 0.5f) { unsigned r = j / 125u;        dst[r - rbase] = (unsigned char)(j - r * 125u); }
                    if (v.y > 0.5f) { unsigned r = (j + 1) / 125u;  dst[r - rbase] = (unsigned char)(j + 1 - r * 125u); }
                    if (v.z > 0.5f) { unsigned r = (j + 2) / 125u;  dst[r - rbase] = (unsigned char)(j + 2 - r * 125u); }
                    if (v.w > 0.5f) { unsigned r = (j + 3) / 125u;  dst[r - rbase] = (unsigned char)(j + 3 - r * 125u); }
                }
            }
            pair_bar(s);   // chunk c ready for both chains
        }
    } else {
        // ------------- scanner warp: chains b0 and b1 interleaved -------------
        // A column k-pairs in registers (chain-invariant):
        float2 aA[32], aB[32];
#pragma unroll
        for (int kp = 0; kp < 32; kp++) {
            aA[kp].x = A[(2 * kp)     * SS + lane];
            aA[kp].y = A[(2 * kp + 1) * SS + lane];
            aB[kp].x = A[(2 * kp)     * SS + lane + 32];
            aB[kp].y = A[(2 * kp + 1) * SS + lane + 32];
        }
        const float i0 = Ivec[lane];
        const float i1 = Ivec[lane + 32];

        float u0X, u1X, u0Y, u1Y;
        int esumX = 0, esumY = 0;

        // ---- t = 0 (chunk 0) ----
        pair_bar(s);
        {
            int obX = sObs[slot0][0][0];
            int obY = sObs[slot1][0][0];
            float2 eX = sB2[obX * 32 + lane];
            float2 eY = sB2[obY * 32 + lane];
            u0X = eX.x * i0;  u1X = eX.y * i1;
            u0Y = eY.x * i0;  u1Y = eY.y * i1;
            sAlpha[slot0][0][lane]      = u0X;
            sAlpha[slot0][0][lane + 32] = u1X;
            sAlpha[slot1][0][lane]      = u0Y;
            sAlpha[slot1][0][lane + 32] = u1Y;
            asm volatile("" ::: "memory");
        }

        for (int c = 0; c < NCHUNK; c++) {
            if (c) pair_bar(s);
            const unsigned char* obpX = sObs[slot0][c & 1];
            const unsigned char* obpY = sObs[slot1][c & 1];
            const int t0 = (c == 0) ? 1 : 0;
            for (int tt = t0; tt < CHUNK; tt++) {
                const int t  = c * CHUNK + tt;
                const int rb = (t - 1) & 1;
                const int wb = t & 1;

                int obX = obpX[tt];
                int obY = obpY[tt];
                float2 eX = sB2[obX * 32 + lane];
                float2 eY = sB2[obY * 32 + lane];

                const float4* apX = (const float4*)sAlpha[slot0][rb];
                const float4* apY = (const float4*)sAlpha[slot1][rb];
                float2 xA0 = {0.f,0.f}, xA1 = {0.f,0.f}, xB0 = {0.f,0.f}, xB1 = {0.f,0.f};
                float2 yA0 = {0.f,0.f}, yA1 = {0.f,0.f}, yB0 = {0.f,0.f}, yB1 = {0.f,0.f};
#pragma unroll
                for (int q = 0; q < 16; q++) {
                    float4 alX = apX[q];
                    float4 alY = apY[q];
                    float2 xlo = make_float2(alX.x, alX.y);
                    float2 xhi = make_float2(alX.z, alX.w);
                    float2 ylo = make_float2(alY.x, alY.y);
                    float2 yhi = make_float2(alY.z, alY.w);
                    ffma2(xA0, xlo, aA[2 * q],     xA0);
                    ffma2(yA0, ylo, aA[2 * q],     yA0);
                    ffma2(xA1, xhi, aA[2 * q + 1], xA1);
                    ffma2(yA1, yhi, aA[2 * q + 1], yA1);
                    ffma2(xB0, xlo, aB[2 * q],     xB0);
                    ffma2(yB0, ylo, aB[2 * q],     yB0);
                    ffma2(xB1, xhi, aB[2 * q + 1], xB1);
                    ffma2(yB1, yhi, aB[2 * q + 1], yB1);
                }
                float r0X = (xA0.x + xA0.y) + (xA1.x + xA1.y);
                float r1X = (xB0.x + xB0.y) + (xB1.x + xB1.y);
                float r0Y = (yA0.x + yA0.y) + (yA1.x + yA1.y);
                float r1Y = (yB0.x + yB0.y) + (yB1.x + yB1.y);
                u0X = eX.x * r0X;  u1X = eX.y * r1X;
                u0Y = eY.x * r0Y;  u1Y = eY.y * r1Y;

                // every 8 steps: exact power-of-two rescale from lane 0's exponent
                if ((t & 7) == 7) {
                    float w0X = __shfl_sync(0xffffffffu, u0X, 0);
                    float w0Y = __shfl_sync(0xffffffffu, u0Y, 0);
                    int exX = (int)((__float_as_uint(w0X) >> 23) & 0xff) - 127;
                    int exY = (int)((__float_as_uint(w0Y) >> 23) & 0xff) - 127;
                    esumX += exX;
                    esumY += exY;
                    float scX = __uint_as_float((unsigned)(127 - exX) << 23);  // 2^-ex
                    float scY = __uint_as_float((unsigned)(127 - exY) << 23);
                    u0X *= scX;  u1X *= scX;
                    u0Y *= scY;  u1Y *= scY;
                }

                sAlpha[slot0][wb][lane]      = u0X;
                sAlpha[slot0][wb][lane + 32] = u1X;
                sAlpha[slot1][wb][lane]      = u0Y;
                sAlpha[slot1][wb][lane + 32] = u1Y;
                // convergent warp: same-warp STS->LDS is HW-ordered; block only
                // compiler reordering across iterations.
                asm volatile("" ::: "memory");
            }
        }

        // single exact reduction + log per chain at the end
        float sX = u0X + u1X;
        float sY = u0Y + u1Y;
#pragma unroll
        for (int o = 16; o; o >>= 1) {
            sX += __shfl_xor_sync(0xffffffffu, sX, o);
            sY += __shfl_xor_sync(0xffffffffu, sY, o);
        }
        if (lane == 0) {
            out[b0] = (float)esumX * 0.6931471805599453f + logf(sX);
            out[b1] = (float)esumY * 0.6931471805599453f + logf(sY);
        }
    }
}

extern "C" void kernel_launch(void* const* d_in, const int* in_sizes, int n_in,
                              void* d_out, int out_size) {
    const float* x  = (const float*)d_in[0];   // [512, 4096, 125]
    const float* I  = (const float*)d_in[1];   // [1, 64]
    const float* A  = (const float*)d_in[2];   // [64, 64]
    const float* Bm = (const float*)d_in[3];   // [125, 64]
    float* out = (float*)d_out;                // [512, 1]

    fused_hmm_kernel<<<BB / 4, 128>>>(x, I, A, Bm, out);
}

// round 10
// speedup vs baseline: 1.9676x; 1.9676x over previous
#include <cuda_runtime.h>
#include <cstdint>

#define BB 512
#define TT 4096
#define SS 64
#define MM 125
#define CHUNK 512                 // time-steps per producer/consumer chunk
#define NCHUNK (TT / CHUNK)       // 8

// packed f32x2 FMA — only reachable via PTX (ptxas never auto-fuses)
__device__ __forceinline__ void ffma2(float2& d, float2 a, float2 b, float2 c) {
    asm("fma.rn.f32x2 %0, %1, %2, %3;"
        : "=l"(*(unsigned long long*)&d)
        : "l"(*(unsigned long long*)&a),
          "l"(*(unsigned long long*)&b),
          "l"(*(unsigned long long*)&c));
}

// pair rendezvous: scanner warp p and decoder warp p+4, named barrier p+1
__device__ __forceinline__ void pair_bar(int p) {
    asm volatile("bar.sync %0, 64;" :: "r"(p + 1) : "memory");
}

// One matvec + emission multiply: u = E .* (alpha @ A), alpha read from rb.
__device__ __forceinline__ void matvec_step(
    const float* __restrict__ rb, float2 e,
    const float2* __restrict__ aA, const float2* __restrict__ aB,
    float& u0, float& u1)
{
    const float4* ap = (const float4*)rb;
    float2 A0 = {0.f,0.f}, A1 = {0.f,0.f}, B0 = {0.f,0.f}, B1 = {0.f,0.f};
#pragma unroll
    for (int q = 0; q < 16; q++) {
        float4 al = ap[q];                       // alpha[4q..4q+3] (broadcast LDS.128)
        float2 lo = make_float2(al.x, al.y);
        float2 hi = make_float2(al.z, al.w);
        ffma2(A0, lo, aA[2 * q],     A0);
        ffma2(A1, hi, aA[2 * q + 1], A1);
        ffma2(B0, lo, aB[2 * q],     B0);
        ffma2(B1, hi, aB[2 * q + 1], B1);
    }
    float r0 = (A0.x + A0.y) + (A1.x + A1.y);
    float r1 = (B0.x + B0.y) + (B1.x + B1.y);
    u0 = e.x * r0;
    u1 = e.y * r1;
}

// 8 steps, straight-line. Even step in block: read buf1, write buf0; odd: the
// reverse (global t parity matches since blocks are 8 long and start even).
// Renorm (exact power-of-two, 1 shfl) only at step 7, before its store.
template<bool INIT>
__device__ __forceinline__ void block8(
    const unsigned char* __restrict__ obs8,
    const float2* __restrict__ sB2,
    float* __restrict__ buf0, float* __restrict__ buf1,
    const float2* __restrict__ aA, const float2* __restrict__ aB,
    float& u0, float& u1, int& esum, int lane, float i0, float i1)
{
    // obs for the whole block in 2 registers; all 8 e-pairs prefetched:
    // independent LDS.64s that pipeline under the first FMA chain.
    uint2 ow = *(const uint2*)obs8;
    float2 e[8];
#pragma unroll
    for (int i = 0; i < 8; i++) {
        unsigned word = (i < 4) ? ow.x : ow.y;
        int ob = (word >> ((i & 3) * 8)) & 0xff;
        e[i] = sB2[ob * 32 + lane];
    }

    if (INIT) {
        u0 = e[0].x * i0;                        // t=0: u = E0 * I (unnormalized)
        u1 = e[0].y * i1;
    } else {
        matvec_step(buf1, e[0], aA, aB, u0, u1);
    }
    buf0[lane]      = u0;
    buf0[lane + 32] = u1;
    asm volatile("" ::: "memory");

#pragma unroll
    for (int i = 1; i < 8; i++) {
        const float* rb = (i & 1) ? buf0 : buf1;
        float*       wb = (i & 1) ? buf1 : buf0;
        matvec_step(rb, e[i], aA, aB, u0, u1);
        if (i == 7) {
            // exact power-of-two rescale from lane 0's exponent; log deferred
            float w0 = __shfl_sync(0xffffffffu, u0, 0);
            int ex = (int)((__float_as_uint(w0) >> 23) & 0xff) - 127;
            esum += ex;
            float sc = __uint_as_float((unsigned)(127 - ex) << 23);   // 2^-ex
            u0 *= sc;
            u1 *= sc;
        }
        wb[lane]      = u0;
        wb[lane + 32] = u1;
        // convergent warp: same-warp STS->LDS is HW-ordered; block only the
        // compiler from reordering smem accesses across steps.
        asm volatile("" ::: "memory");
    }
}

// ---------------------------------------------------------------------------
// Fused kernel, 256 threads/CTA:
//   warps 0-3 : scanner warps, one chain each
//   warps 4-7 : decoder warps, stream + argmax-decode the partner chain
// ---------------------------------------------------------------------------
__global__ void __launch_bounds__(256) fused_hmm_kernel(
    const float* __restrict__ x,
    const float* __restrict__ Ivec,
    const float* __restrict__ A,
    const float* __restrict__ Bm,
    float* __restrict__ out)
{
    __shared__ float2 sB2[MM * 32];                          // 32000 B
    __shared__ float sAlpha[4][2][SS];                       //  2048 B
    __shared__ __align__(16) unsigned char sObs[4][2][CHUNK];//  4096 B

    const int tid  = threadIdx.x;
    const int w    = tid >> 5;          // 0..7
    const int lane = tid & 31;
    const int p    = w & 3;             // chain slot / pair id
    const int b    = blockIdx.x * 4 + p;

    // stage Bm into shared as (Bm[m][l], Bm[m][l+32]) pairs
    for (int i = tid; i < MM * 32; i += 256) {
        int m = i >> 5, l = i & 31;
        sB2[i] = make_float2(Bm[m * SS + l], Bm[m * SS + 32 + l]);
    }
    __syncthreads();

    if (w >= 4) {
        // ------------------ decoder warp for chain b ------------------
        const float4* xc = (const float4*)(x + (size_t)b * TT * MM);
        for (int c = 0; c < NCHUNK; c++) {
            unsigned char* dst = sObs[p][c & 1];
            const float4* base = xc + c * (CHUNK * MM / 4);   // 16000 float4/chunk
            const unsigned jbase = c * (CHUNK * MM);
            const unsigned rbase = c * CHUNK;
            for (int i = lane; i < CHUNK * MM / 4; i += 32) {
                float4 v = __ldcs(base + i);
                unsigned j = jbase + 4u * i;
                if (v.x > 0.5f) { unsigned r = j / 125u;        dst[r - rbase] = (unsigned char)(j - r * 125u); }
                if (v.y > 0.5f) { unsigned r = (j + 1) / 125u;  dst[r - rbase] = (unsigned char)(j + 1 - r * 125u); }
                if (v.z > 0.5f) { unsigned r = (j + 2) / 125u;  dst[r - rbase] = (unsigned char)(j + 2 - r * 125u); }
                if (v.w > 0.5f) { unsigned r = (j + 3) / 125u;  dst[r - rbase] = (unsigned char)(j + 3 - r * 125u); }
            }
            pair_bar(p);   // chunk c ready; scanner freed the other buffer by arriving
        }
    } else {
        // ------------------ scanner warp for chain b ------------------
        // A column k-pairs in registers (loop-invariant):
        float2 aA[32], aB[32];
#pragma unroll
        for (int kp = 0; kp < 32; kp++) {
            aA[kp].x = A[(2 * kp)     * SS + lane];
            aA[kp].y = A[(2 * kp + 1) * SS + lane];
            aB[kp].x = A[(2 * kp)     * SS + lane + 32];
            aB[kp].y = A[(2 * kp + 1) * SS + lane + 32];
        }
        const float i0 = Ivec[lane];
        const float i1 = Ivec[lane + 32];

        float* buf0 = sAlpha[p][0];
        float* buf1 = sAlpha[p][1];
        float u0, u1;
        int esum = 0;

        // ---- chunk 0 ----
        pair_bar(p);
        {
            const unsigned char* ob = sObs[p][0];
            block8<true>(ob, sB2, buf0, buf1, aA, aB, u0, u1, esum, lane, i0, i1);
            for (int blk = 1; blk < CHUNK / 8; blk++)
                block8<false>(ob + blk * 8, sB2, buf0, buf1, aA, aB, u0, u1, esum, lane, i0, i1);
        }
        // ---- chunks 1..7 ----
        for (int c = 1; c < NCHUNK; c++) {
            pair_bar(p);
            const unsigned char* ob = sObs[p][c & 1];
            for (int blk = 0; blk < CHUNK / 8; blk++)
                block8<false>(ob + blk * 8, sB2, buf0, buf1, aA, aB, u0, u1, esum, lane, i0, i1);
        }

        // single exact reduction + log at the end:
        float s = u0 + u1;
#pragma unroll
        for (int o = 16; o; o >>= 1) s += __shfl_xor_sync(0xffffffffu, s, o);
        if (lane == 0) out[b] = (float)esum * 0.6931471805599453f + logf(s);
    }
}

extern "C" void kernel_launch(void* const* d_in, const int* in_sizes, int n_in,
                              void* d_out, int out_size) {
    const float* x  = (const float*)d_in[0];   // [512, 4096, 125]
    const float* I  = (const float*)d_in[1];   // [1, 64]
    const float* A  = (const float*)d_in[2];   // [64, 64]
    const float* Bm = (const float*)d_in[3];   // [125, 64]
    float* out = (float*)d_out;                // [512, 1]

    fused_hmm_kernel<<<BB / 4, 256>>>(x, I, A, Bm, out);
}

// round 11
// speedup vs baseline: 1.9925x; 1.0127x over previous
#include <cuda_runtime.h>
#include <cstdint>

#define BB 512
#define TT 4096
#define SS 64
#define MM 125
#define CHUNK 512                 // time-steps per producer/consumer chunk
#define NCHUNK (TT / CHUNK)       // 8

// packed f32x2 FMA — only reachable via PTX (ptxas never auto-fuses)
__device__ __forceinline__ void ffma2(float2& d, float2 a, float2 b, float2 c) {
    asm("fma.rn.f32x2 %0, %1, %2, %3;"
        : "=l"(*(unsigned long long*)&d)
        : "l"(*(unsigned long long*)&a),
          "l"(*(unsigned long long*)&b),
          "l"(*(unsigned long long*)&c));
}

// pair rendezvous: scanner warp p and decoder warp p+4, named barrier p+1
__device__ __forceinline__ void pair_bar(int p) {
    asm volatile("bar.sync %0, 64;" :: "r"(p + 1) : "memory");
}

// One step's matvec with ALL 16 alpha float4s hoisted into registers first,
// so no LDS latency is exposed inside the FMA chain.
// Alpha buffer layout is interleaved: float2 slot l = (alpha[l], alpha[l+32]),
// so float4 q = [a_{2q}, a_{2q+32}, a_{2q+1}, a_{2q+33}]; the A-register table
// is permuted to match (see load below).
__device__ __forceinline__ void matvec_step(
    const float2* __restrict__ rb2, float2 e,
    const float2* __restrict__ aA, const float2* __restrict__ aB,
    float& u0, float& u1)
{
    const float4* ap = (const float4*)rb2;
    float4 alf[16];
#pragma unroll
    for (int q = 0; q < 16; q++) alf[q] = ap[q];   // 16 LDS.128, issued back-to-back

    float2 A0 = {0.f,0.f}, A1 = {0.f,0.f}, B0 = {0.f,0.f}, B1 = {0.f,0.f};
#pragma unroll
    for (int q = 0; q < 16; q++) {
        float2 lo = make_float2(alf[q].x, alf[q].y);   // (a_{2q},   a_{2q+32})
        float2 hi = make_float2(alf[q].z, alf[q].w);   // (a_{2q+1}, a_{2q+33})
        ffma2(A0, lo, aA[2 * q],     A0);
        ffma2(A1, hi, aA[2 * q + 1], A1);
        ffma2(B0, lo, aB[2 * q],     B0);
        ffma2(B1, hi, aB[2 * q + 1], B1);
    }
    float r0 = (A0.x + A0.y) + (A1.x + A1.y);
    float r1 = (B0.x + B0.y) + (B1.x + B1.y);
    u0 = e.x * r0;
    u1 = e.y * r1;
}

// 8 straight-line steps; static buffer parity; renorm only at step 7.
template<bool INIT>
__device__ __forceinline__ void block8(
    const unsigned char* __restrict__ obs8,
    const float2* __restrict__ sB2,
    float2* __restrict__ buf0, float2* __restrict__ buf1,
    const float2* __restrict__ aA, const float2* __restrict__ aB,
    float& u0, float& u1, int& esum, int lane, float i0, float i1)
{
    uint2 ow = *(const uint2*)obs8;      // 8 obs bytes in 2 registers

#pragma unroll
    for (int i = 0; i < 8; i++) {
        unsigned word = (i < 4) ? ow.x : ow.y;
        int ob = (word >> ((i & 3) * 8)) & 0xff;
        float2 e = sB2[ob * 32 + lane];  // issued first; latency hides under FMAs

        if (INIT && i == 0) {
            u0 = e.x * i0;               // t=0: u = E0 * I (unnormalized)
            u1 = e.y * i1;
        } else {
            const float2* rb = (i & 1) ? buf0 : buf1;
            matvec_step(rb, e, aA, aB, u0, u1);
        }

        if (i == 7) {
            // exact power-of-two rescale from lane 0's exponent; log deferred
            float w0 = __shfl_sync(0xffffffffu, u0, 0);
            int ex = (int)((__float_as_uint(w0) >> 23) & 0xff) - 127;
            esum += ex;
            float sc = __uint_as_float((unsigned)(127 - ex) << 23);   // 2^-ex
            u0 *= sc;
            u1 *= sc;
        }

        float2* wb = (i & 1) ? buf1 : buf0;
        wb[lane] = make_float2(u0, u1);  // single STS.64, interleaved layout
        // convergent warp: same-warp STS->LDS is HW-ordered; block only the
        // compiler from reordering smem accesses across steps.
        asm volatile("" ::: "memory");
    }
}

// ---------------------------------------------------------------------------
// Fused kernel, 256 threads/CTA:
//   warps 0-3 : scanner warps, one chain each
//   warps 4-7 : decoder warps, stream + argmax-decode the partner chain
// ---------------------------------------------------------------------------
__global__ void __launch_bounds__(256, 1) fused_hmm_kernel(
    const float* __restrict__ x,
    const float* __restrict__ Ivec,
    const float* __restrict__ A,
    const float* __restrict__ Bm,
    float* __restrict__ out)
{
    __shared__ float2 sB2[MM * 32];                          // 32000 B
    __shared__ float2 sAlpha[4][2][32];                      //  2048 B (interleaved pairs)
    __shared__ __align__(16) unsigned char sObs[4][2][CHUNK];//  4096 B

    const int tid  = threadIdx.x;
    const int w    = tid >> 5;          // 0..7
    const int lane = tid & 31;
    const int p    = w & 3;             // chain slot / pair id
    const int b    = blockIdx.x * 4 + p;

    // stage Bm into shared as (Bm[m][l], Bm[m][l+32]) pairs
    for (int i = tid; i < MM * 32; i += 256) {
        int m = i >> 5, l = i & 31;
        sB2[i] = make_float2(Bm[m * SS + l], Bm[m * SS + 32 + l]);
    }
    __syncthreads();

    if (w >= 4) {
        // ------------------ decoder warp for chain b ------------------
        const float4* xc = (const float4*)(x + (size_t)b * TT * MM);
        for (int c = 0; c < NCHUNK; c++) {
            unsigned char* dst = sObs[p][c & 1];
            const float4* base = xc + c * (CHUNK * MM / 4);   // 16000 float4/chunk
            const unsigned jbase = c * (CHUNK * MM);
            const unsigned rbase = c * CHUNK;
            for (int i = lane; i < CHUNK * MM / 4; i += 32) {
                float4 v = __ldcs(base + i);
                unsigned j = jbase + 4u * i;
                if (v.x > 0.5f) { unsigned r = j / 125u;        dst[r - rbase] = (unsigned char)(j - r * 125u); }
                if (v.y > 0.5f) { unsigned r = (j + 1) / 125u;  dst[r - rbase] = (unsigned char)(j + 1 - r * 125u); }
                if (v.z > 0.5f) { unsigned r = (j + 2) / 125u;  dst[r - rbase] = (unsigned char)(j + 2 - r * 125u); }
                if (v.w > 0.5f) { unsigned r = (j + 3) / 125u;  dst[r - rbase] = (unsigned char)(j + 3 - r * 125u); }
            }
            pair_bar(p);   // chunk c ready; scanner freed the other buffer by arriving
        }
    } else {
        // ------------------ scanner warp for chain b ------------------
        // A-register table, permuted to match the interleaved alpha layout:
        //  aA[2q]   = (A[2q][l],   A[2q+32][l]);  aA[2q+1] = (A[2q+1][l], A[2q+33][l])
        //  aB same with column l+32.
        float2 aA[32], aB[32];
#pragma unroll
        for (int q = 0; q < 16; q++) {
            aA[2 * q].x     = A[(2 * q)      * SS + lane];
            aA[2 * q].y     = A[(2 * q + 32) * SS + lane];
            aA[2 * q + 1].x = A[(2 * q + 1)  * SS + lane];
            aA[2 * q + 1].y = A[(2 * q + 33) * SS + lane];
            aB[2 * q].x     = A[(2 * q)      * SS + lane + 32];
            aB[2 * q].y     = A[(2 * q + 32) * SS + lane + 32];
            aB[2 * q + 1].x = A[(2 * q + 1)  * SS + lane + 32];
            aB[2 * q + 1].y = A[(2 * q + 33) * SS + lane + 32];
        }
        const float i0 = Ivec[lane];
        const float i1 = Ivec[lane + 32];

        float2* buf0 = sAlpha[p][0];
        float2* buf1 = sAlpha[p][1];
        float u0, u1;
        int esum = 0;

        // ---- chunk 0 ----
        pair_bar(p);
        {
            const unsigned char* ob = sObs[p][0];
            block8<true>(ob, sB2, buf0, buf1, aA, aB, u0, u1, esum, lane, i0, i1);
            for (int blk = 1; blk < CHUNK / 8; blk++)
                block8<false>(ob + blk * 8, sB2, buf0, buf1, aA, aB, u0, u1, esum, lane, i0, i1);
        }
        // ---- chunks 1..7 ----
        for (int c = 1; c < NCHUNK; c++) {
            pair_bar(p);
            const unsigned char* ob = sObs[p][c & 1];
            for (int blk = 0; blk < CHUNK / 8; blk++)
                block8<false>(ob + blk * 8, sB2, buf0, buf1, aA, aB, u0, u1, esum, lane, i0, i1);
        }

        // single exact reduction + log at the end:
        float s = u0 + u1;
#pragma unroll
        for (int o = 16; o; o >>= 1) s += __shfl_xor_sync(0xffffffffu, s, o);
        if (lane == 0) out[b] = (float)esum * 0.6931471805599453f + logf(s);
    }
}

extern "C" void kernel_launch(void* const* d_in, const int* in_sizes, int n_in,
                              void* d_out, int out_size) {
    const float* x  = (const float*)d_in[0];   // [512, 4096, 125]
    const float* I  = (const float*)d_in[1];   // [1, 64]
    const float* A  = (const float*)d_in[2];   // [64, 64]
    const float* Bm = (const float*)d_in[3];   // [125, 64]
    float* out = (float*)d_out;                // [512, 1]

    fused_hmm_kernel<<<BB / 4, 256>>>(x, I, A, Bm, out);
}